// round 11
// baseline (speedup 1.0000x reference)
#include <cuda_runtime.h>
#include <cuda_fp16.h>
#include <cstdint>

// ---------------- problem constants ----------------
#define Gc    16
#define Kt    5
#define IPG   64
#define OPG   64
#define Lr    4096
#define Br    4
#define TILE_M 256
#define CHAIN  2
#define XROWS  (TILE_M + 4)     // 260 rows incl. +/-2 halo
#define NTHR   512

// ---------------- smem layout (bytes) ----------------
#define SM_XH    0                                 // 260*128 = 33280 (fp16 X, swizzled)
#define SM_STAGE 33280                             // 260*256 = 66560 (raw f32 staging)
#define SM_POS   99840                             // 260 ints = 1040
#define SM_ZERO  101120                            // 128B zero block (128B aligned)
#define SM_TOTAL 101248

// ---------------- W fragment scratch ----------------
// [g][tap][ks][wn][p][r][kq] uint4 = paired-nj fp16 B frags
// per g: 5*4*128 = 2560 uint4 (40KB) — read via LDG (L1-cached), no smem stage
__device__ uint4 g_wfrag[Gc * 2560];

__device__ __forceinline__ uint32_t pack_h2(__half a, __half b) {
    return (uint32_t)__half_as_ushort(a) | ((uint32_t)__half_as_ushort(b) << 16);
}

// w input layout: w[g][o][i][k], flat = ((g*64+o)*64+i)*5+k
__global__ void build_wfrag_kernel(const float* __restrict__ w) {
    int idx = blockIdx.x * blockDim.x + threadIdx.x;
    if (idx >= Gc * 2560) return;
    int g    = idx / 2560;
    int rem  = idx % 2560;          // (tap*4+ks)*128 + wn*64 + p*32 + r*4 + kq
    int tapks = rem >> 7;
    int tap  = tapks >> 2;
    int ks   = tapks & 3;
    int sub  = rem & 127;
    int wn   = sub >> 6;
    int p    = (sub >> 5) & 1;
    int r    = (sub >> 2) & 7;
    int kq   = sub & 3;

    int i0 = ks * 16 + kq * 2;
    int nA = wn * 32 + (2 * p)     * 8 + r;
    int nB = wn * 32 + (2 * p + 1) * 8 + r;

    const float* wA = w + (((size_t)g * OPG + nA) * IPG) * Kt + tap;
    const float* wB = w + (((size_t)g * OPG + nB) * IPG) * Kt + tap;

    uint4 outv;
    outv.x = pack_h2(__float2half(wA[(i0 + 0) * Kt]), __float2half(wA[(i0 + 1) * Kt]));
    outv.y = pack_h2(__float2half(wA[(i0 + 8) * Kt]), __float2half(wA[(i0 + 9) * Kt]));
    outv.z = pack_h2(__float2half(wB[(i0 + 0) * Kt]), __float2half(wB[(i0 + 1) * Kt]));
    outv.w = pack_h2(__float2half(wB[(i0 + 8) * Kt]), __float2half(wB[(i0 + 9) * Kt]));
    g_wfrag[idx] = outv;
}

// ---------------- ptx helpers ----------------
__device__ __forceinline__ uint32_t smem_u32(const void* p) {
    uint32_t a;
    asm("{ .reg .u64 t; cvta.to.shared.u64 t, %1; cvt.u32.u64 %0, t; }" : "=r"(a) : "l"(p));
    return a;
}
__device__ __forceinline__ void ldsm4(uint32_t (&r)[4], uint32_t addr) {
    asm volatile("ldmatrix.sync.aligned.m8n8.x4.shared.b16 {%0,%1,%2,%3}, [%4];"
                 : "=r"(r[0]), "=r"(r[1]), "=r"(r[2]), "=r"(r[3]) : "r"(addr));
}
__device__ __forceinline__ void mma16816(float (&d)[4], const uint32_t (&a)[4],
                                         uint32_t b0, uint32_t b1) {
    asm volatile("mma.sync.aligned.m16n8k16.row.col.f32.f16.f16.f32 "
                 "{%0,%1,%2,%3}, {%4,%5,%6,%7}, {%8,%9}, {%0,%1,%2,%3};"
                 : "+f"(d[0]), "+f"(d[1]), "+f"(d[2]), "+f"(d[3])
                 : "r"(a[0]), "r"(a[1]), "r"(a[2]), "r"(a[3]), "r"(b0), "r"(b1));
}
__device__ __forceinline__ void cp_async16(uint32_t dst, const void* src, int sz) {
    asm volatile("cp.async.ca.shared.global [%0], [%1], 16, %2;"
                 :: "r"(dst), "l"(src), "r"(sz) : "memory");
}
#define CP_COMMIT() asm volatile("cp.async.commit_group;" ::: "memory")
#define CP_WAIT0()  asm volatile("cp.async.wait_group 0;" ::: "memory")

// ---------------- main kernel ----------------
// 512 threads = 16 warps: warp grid 8(m) x 2(n); warp tile m32 x n32
// persistent 2-tile chain with cp.async staging of next tile's raw f32 X
__global__ __launch_bounds__(NTHR, 2)
void conv_hmma_kernel(const float* __restrict__ inp,
                      const int* __restrict__ pos,
                      float* __restrict__ out) {
    extern __shared__ char smem[];
    const uint32_t sb = smem_u32(smem);
    const int tid = threadIdx.x;
    const int lam = tid & 31, wid = tid >> 5;
    const int wm = wid & 7, wn = wid >> 3;
    const int g = blockIdx.y, b = blockIdx.z;
    const int lt_base = blockIdx.x * (TILE_M * CHAIN);
    const int* posb = pos + (size_t)b * Lr;

    const uint32_t xh_base = sb + SM_XH;
    const uint32_t stage_base = sb + SM_STAGE;
    const uint32_t zeroblk = sb + SM_ZERO;
    const int arow = lam & 15;
    const uint32_t hi16q = (uint32_t)(lam >> 4);
    const int row_m0 = wm * 32 + arow;
    const int row_m1 = row_m0 + 16;
    const int* poss = (const int*)(smem + SM_POS);

    // per-lane B fragment base pointer
    const uint4* __restrict__ wgp =
        g_wfrag + (size_t)g * 2560 + (wn * 64 + (lam >> 2) * 4 + (lam & 3));

    // ---- prefetch tile 0 into staging ----
    #pragma unroll
    for (int it = 0; it < 9; it++) {
        int idx = tid + it * NTHR;
        if (idx < XROWS * 16) {
            int r = idx >> 4, c4 = idx & 15;
            int gl = lt_base - 2 + r;
            int ok = (gl >= 0 && gl < Lr);
            int glc = ok ? gl : 0;
            const float4* src = (const float4*)(inp + ((size_t)b * Lr + glc) * 1024 + g * IPG) + c4;
            cp_async16(stage_base + r * 256 + c4 * 16, src, ok ? 16 : 0);
        }
    }
    CP_COMMIT();

    for (int t = 0; t < CHAIN; t++) {
        const int lt = lt_base + t * TILE_M;

        CP_WAIT0();
        __syncthreads();   // staging ready; previous tile's mainloop done

        // ---- pos rows for this tile; zero block (once) ----
        if (tid < XROWS) {
            int gl = lt - 2 + tid;
            ((int*)(smem + SM_POS))[tid] = (gl >= 0 && gl < Lr) ? __ldg(posb + gl) : -100000;
        }
        if (t == 0 && tid < 8) ((uint4*)(smem + SM_ZERO))[tid] = make_uint4(0, 0, 0, 0);

        // ---- convert staging f32 -> fp16 swizzled ----
        for (int e = tid; e < XROWS * 16; e += NTHR) {
            int c4 = e & 15, r = e >> 4;
            float4 v = *(const float4*)(smem + SM_STAGE + r * 256 + c4 * 16);
            __half2 h01 = __float22half2_rn(make_float2(v.x, v.y));
            __half2 h23 = __float22half2_rn(make_float2(v.z, v.w));
            uint32_t off = r * 128 + (((c4 >> 1) ^ (r & 7)) << 4) + (c4 & 1) * 8;
            *(uint2*)(smem + SM_XH + off) =
                make_uint2(*(uint32_t*)&h01, *(uint32_t*)&h23);
        }
        __syncthreads();   // fp16 ready; staging fully consumed

        // ---- prefetch next tile while computing this one ----
        if (t + 1 < CHAIN) {
            int ltn = lt + TILE_M;
            #pragma unroll
            for (int it = 0; it < 9; it++) {
                int idx = tid + it * NTHR;
                if (idx < XROWS * 16) {
                    int r = idx >> 4, c4 = idx & 15;
                    int gl = ltn - 2 + r;
                    int ok = (gl >= 0 && gl < Lr);
                    int glc = ok ? gl : 0;
                    const float4* src = (const float4*)(inp + ((size_t)b * Lr + glc) * 1024 + g * IPG) + c4;
                    cp_async16(stage_base + r * 256 + c4 * 16, src, ok ? 16 : 0);
                }
            }
            CP_COMMIT();
        }

        // ---- per-lane mask flags ----
        uint32_t flags = 0;
        #pragma unroll
        for (int tap = 0; tap < Kt; tap++) {
            int ls0 = lt + row_m0 + tap - 2;
            int ls1 = lt + row_m1 + tap - 2;
            if (ls0 >= 0 && ls0 < Lr && poss[row_m0 + tap] == poss[row_m0 + 2] + (tap - 2))
                flags |= 1u << (tap * 2);
            if (ls1 >= 0 && ls1 < Lr && poss[row_m1 + tap] == poss[row_m1 + 2] + (tap - 2))
                flags |= 1u << (tap * 2 + 1);
        }

        float facc[2][4][4];
        #pragma unroll
        for (int mi = 0; mi < 2; mi++)
            #pragma unroll
            for (int nj = 0; nj < 4; nj++)
                #pragma unroll
                for (int c = 0; c < 4; c++) facc[mi][nj][c] = 0.f;

        // ---- mainloop: 5 taps x 4 k-steps x (2 ldsm + 2 LDG.128 + 8 MMAs) ----
        #pragma unroll
        for (int tap = 0; tap < Kt; tap++) {
            uint32_t base0 = (flags >> (tap * 2)) & 1
                           ? xh_base + (uint32_t)(row_m0 + tap) * 128 : zeroblk;
            uint32_t base1 = (flags >> (tap * 2 + 1)) & 1
                           ? xh_base + (uint32_t)(row_m1 + tap) * 128 : zeroblk;
            uint32_t r7t = (uint32_t)((arow + tap) & 7);

            #pragma unroll
            for (int ks = 0; ks < 4; ks++) {
                uint32_t swz = ((((uint32_t)(ks * 2) + hi16q) ^ r7t) << 4);
                uint32_t a0[4], a1[4];
                ldsm4(a0, base0 + swz);
                ldsm4(a1, base1 + swz);
                uint4 bb01 = __ldg(wgp + (tap * 4 + ks) * 128);
                uint4 bb23 = __ldg(wgp + (tap * 4 + ks) * 128 + 32);

                mma16816(facc[0][0], a0, bb01.x, bb01.y);
                mma16816(facc[1][0], a1, bb01.x, bb01.y);
                mma16816(facc[0][1], a0, bb01.z, bb01.w);
                mma16816(facc[1][1], a1, bb01.z, bb01.w);
                mma16816(facc[0][2], a0, bb23.x, bb23.y);
                mma16816(facc[1][2], a1, bb23.x, bb23.y);
                mma16816(facc[0][3], a0, bb23.z, bb23.w);
                mma16816(facc[1][3], a1, bb23.z, bb23.w);
            }
        }

        // ---- epilogue: out[b][l][g][o] ----
        #pragma unroll
        for (int mi = 0; mi < 2; mi++) {
            int row0 = wm * 32 + mi * 16 + (lam >> 2);
            #pragma unroll
            for (int nj = 0; nj < 4; nj++) {
                int col = wn * 32 + nj * 8 + (lam & 3) * 2;
                size_t base = (((size_t)b * Lr + lt + row0) * Gc + g) * OPG + col;
                *(float2*)(out + base) = make_float2(facc[mi][nj][0], facc[mi][nj][1]);
                *(float2*)(out + base + (size_t)8 * Gc * OPG) =
                    make_float2(facc[mi][nj][2], facc[mi][nj][3]);
            }
        }
    }
}

extern "C" void kernel_launch(void* const* d_in, const int* in_sizes, int n_in,
                              void* d_out, int out_size) {
    const float* inp = (const float*)d_in[0];   // (4, 4096, 1024) f32
    const int*   pos = (const int*)d_in[1];     // (4, 4096) i32
    const float* w   = (const float*)d_in[2];   // (16, 64, 64, 5) f32
    float* out = (float*)d_out;                 // (4, 4096, 16, 64) f32

    build_wfrag_kernel<<<(Gc * 2560 + 255) / 256, 256>>>(w);

    cudaFuncSetAttribute(conv_hmma_kernel,
                         cudaFuncAttributeMaxDynamicSharedMemorySize, SM_TOTAL);
    dim3 grid(Lr / (TILE_M * CHAIN), Gc, Br);   // (8, 16, 4)
    conv_hmma_kernel<<<grid, NTHR, SM_TOTAL>>>(inp, pos, out);
}

// round 12
// speedup vs baseline: 1.1757x; 1.1757x over previous
#include <cuda_runtime.h>
#include <cuda_fp16.h>
#include <cstdint>

// ---------------- problem constants ----------------
#define Gc    16
#define Kt    5
#define IPG   64
#define OPG   64
#define Lr    4096
#define Br    4
#define TILE_M 256
#define XROWS  (TILE_M + 4)     // 260 rows incl. +/-2 halo
#define NTHR   512

// ---------------- smem layout (bytes) ----------------
#define SM_XH   0                                  // 260*128 = 33280 (fp16 X, swizzled)
#define SM_W    33280                              // 5120 uint2 = 40960
#define SM_POS  74240                              // 260 ints = 1040
#define SM_ZERO 75392                              // 128B zero block (128B aligned)
#define SM_TOTAL 75520

// ---------------- W fragment scratch ----------------
// [g][tap][kc][o][q] uint2 = {b0,b1} fp16 frags; per g: 5*4*64*4 = 5120 uint2
__device__ uint2 g_wfrag[Gc * 5120];

__device__ __forceinline__ uint32_t pack_h2(__half a, __half b) {
    return (uint32_t)__half_as_ushort(a) | ((uint32_t)__half_as_ushort(b) << 16);
}

// ---- staged, coalesced W packer: 64 blocks (4 per g, 16 o-rows each) ----
// w layout: w[g][o][i][k], flat = ((g*64+o)*64+i)*5+k
__global__ __launch_bounds__(256)
void build_wfrag_kernel(const float* __restrict__ w) {
    __shared__ float ws[16 * IPG * Kt];            // 16 o-rows x 320 floats = 20480B
    const int g  = blockIdx.x >> 2;
    const int o0 = (blockIdx.x & 3) * 16;
    const int tid = threadIdx.x;

    // coalesced stage: 5120 consecutive floats -> 1280 float4
    const float4* src = (const float4*)(w + (((size_t)g * OPG + o0) * IPG) * Kt);
    #pragma unroll
    for (int it = 0; it < 5; it++)
        ((float4*)ws)[tid + it * 256] = src[tid + it * 256];
    __syncthreads();

    // emit 1280 uint2 fragments, coalesced writes
    #pragma unroll
    for (int it = 0; it < 5; it++) {
        int e = tid + it * 256;                    // [tapkc(20)][o_l(16)][q(4)]
        int tapkc = e >> 6;
        int tap = tapkc / 4, kc = tapkc & 3;
        int sub = e & 63;
        int o_l = sub >> 2, q = sub & 3;
        int i0 = kc * 16 + q * 2;
        const float* r = ws + o_l * (IPG * Kt) + tap;
        uint2 outv;
        outv.x = pack_h2(__float2half(r[(i0 + 0) * Kt]), __float2half(r[(i0 + 1) * Kt]));
        outv.y = pack_h2(__float2half(r[(i0 + 8) * Kt]), __float2half(r[(i0 + 9) * Kt]));
        g_wfrag[(size_t)g * 5120 + (tapkc << 8) + ((o0 + o_l) * 4 + q)] = outv;
    }
}

// ---------------- ptx helpers ----------------
__device__ __forceinline__ uint32_t smem_u32(const void* p) {
    uint32_t a;
    asm("{ .reg .u64 t; cvta.to.shared.u64 t, %1; cvt.u32.u64 %0, t; }" : "=r"(a) : "l"(p));
    return a;
}
__device__ __forceinline__ void ldsm4(uint32_t (&r)[4], uint32_t addr) {
    asm volatile("ldmatrix.sync.aligned.m8n8.x4.shared.b16 {%0,%1,%2,%3}, [%4];"
                 : "=r"(r[0]), "=r"(r[1]), "=r"(r[2]), "=r"(r[3]) : "r"(addr));
}
__device__ __forceinline__ void mma16816(float (&d)[4], const uint32_t (&a)[4],
                                         uint32_t b0, uint32_t b1) {
    asm volatile("mma.sync.aligned.m16n8k16.row.col.f32.f16.f16.f32 "
                 "{%0,%1,%2,%3}, {%4,%5,%6,%7}, {%8,%9}, {%0,%1,%2,%3};"
                 : "+f"(d[0]), "+f"(d[1]), "+f"(d[2]), "+f"(d[3])
                 : "r"(a[0]), "r"(a[1]), "r"(a[2]), "r"(a[3]), "r"(b0), "r"(b1));
}

// ---------------- main kernel (round-6 best: 512 thr, 16 warps 8m x 2n) ----------------
__global__ __launch_bounds__(NTHR, 2)
void conv_hmma_kernel(const float* __restrict__ inp,
                      const int* __restrict__ pos,
                      float* __restrict__ out) {
    extern __shared__ char smem[];
    const int tid = threadIdx.x;
    const int lam = tid & 31, wid = tid >> 5;
    const int wm = wid & 7, wn = wid >> 3;
    const int g = blockIdx.y, b = blockIdx.z;
    const int lt = blockIdx.x * TILE_M;
    const int* posb = pos + (size_t)b * Lr;

    // ---- stage W fragments ----
    {
        const uint4* wsrc = (const uint4*)(g_wfrag + (size_t)g * 5120);
        uint4* wdst = (uint4*)(smem + SM_W);
        #pragma unroll
        for (int it = 0; it < 5; it++)
            wdst[tid + it * NTHR] = wsrc[tid + it * NTHR];
    }

    // ---- stage pos rows [lt-2, lt+258) with OOB sentinel; zero block ----
    {
        int* poss = (int*)(smem + SM_POS);
        if (tid < XROWS) {
            int gl = lt - 2 + tid;
            poss[tid] = (gl >= 0 && gl < Lr) ? __ldg(posb + gl) : -100000;
        }
        if (tid < 8) ((uint4*)(smem + SM_ZERO))[tid] = make_uint4(0, 0, 0, 0);
    }

    // ---- convert X rows to fp16, swizzled 128B rows ----
    for (int e = tid; e < XROWS * 16; e += NTHR) {
        int c4 = e & 15, r = e >> 4;
        int gl = lt - 2 + r;
        float4 v = make_float4(0.f, 0.f, 0.f, 0.f);
        if (gl >= 0 && gl < Lr)
            v = __ldg((const float4*)(inp + ((size_t)b * Lr + gl) * 1024 + g * IPG) + c4);

        __half2 h01 = __float22half2_rn(make_float2(v.x, v.y));
        __half2 h23 = __float22half2_rn(make_float2(v.z, v.w));

        uint32_t off = r * 128 + (((c4 >> 1) ^ (r & 7)) << 4) + (c4 & 1) * 8;
        *(uint2*)(smem + SM_XH + off) =
            make_uint2(*(uint32_t*)&h01, *(uint32_t*)&h23);
    }
    __syncthreads();

    // ---- per-lane mask flags (10 bits: tap*2 + mi) ----
    const uint32_t sb = smem_u32(smem);
    const uint32_t xh_base = sb + SM_XH;
    const uint32_t zeroblk = sb + SM_ZERO;
    const int arow = lam & 15;
    const uint32_t hi16q = (uint32_t)(lam >> 4);     // 0 or 1: col-half selector
    const int row_m0 = wm * 32 + arow;               // A rows for mi=0 / mi=1
    const int row_m1 = row_m0 + 16;
    const int* poss = (const int*)(smem + SM_POS);

    uint32_t flags = 0;
    #pragma unroll
    for (int tap = 0; tap < Kt; tap++) {
        int ls0 = lt + row_m0 + tap - 2;
        int ls1 = lt + row_m1 + tap - 2;
        if (ls0 >= 0 && ls0 < Lr && poss[row_m0 + tap] == poss[row_m0 + 2] + (tap - 2))
            flags |= 1u << (tap * 2);
        if (ls1 >= 0 && ls1 < Lr && poss[row_m1 + tap] == poss[row_m1 + 2] + (tap - 2))
            flags |= 1u << (tap * 2 + 1);
    }

    const uint2* wsm = (const uint2*)(smem + SM_W);
    const int bq = (wn * 32 + (lam >> 2)) * 4 + (lam & 3);

    float facc[2][4][4];
    #pragma unroll
    for (int mi = 0; mi < 2; mi++)
        #pragma unroll
        for (int nj = 0; nj < 4; nj++)
            #pragma unroll
            for (int c = 0; c < 4; c++) facc[mi][nj][c] = 0.f;

    // ---- mainloop: 5 taps x 4 k-steps x (2 ldsm + 8 MMAs) ----
    #pragma unroll
    for (int tap = 0; tap < Kt; tap++) {
        uint32_t base0 = (flags >> (tap * 2)) & 1
                       ? xh_base + (uint32_t)(row_m0 + tap) * 128 : zeroblk;
        uint32_t base1 = (flags >> (tap * 2 + 1)) & 1
                       ? xh_base + (uint32_t)(row_m1 + tap) * 128 : zeroblk;
        uint32_t r7t = (uint32_t)((arow + tap) & 7);

        #pragma unroll
        for (int ks = 0; ks < 4; ks++) {
            uint32_t swz = ((((uint32_t)(ks * 2) + hi16q) ^ r7t) << 4);
            uint32_t a0[4], a1[4];
            ldsm4(a0, base0 + swz);
            ldsm4(a1, base1 + swz);

            #pragma unroll
            for (int nj = 0; nj < 4; nj++) {
                uint2 bb = wsm[(tap * 4 + ks) * 256 + bq + nj * 32];
                mma16816(facc[0][nj], a0, bb.x, bb.y);
                mma16816(facc[1][nj], a1, bb.x, bb.y);
            }
        }
    }

    // ---- epilogue: out[b][l][g][o] ----
    #pragma unroll
    for (int mi = 0; mi < 2; mi++) {
        int row0 = wm * 32 + mi * 16 + (lam >> 2);
        #pragma unroll
        for (int nj = 0; nj < 4; nj++) {
            int col = wn * 32 + nj * 8 + (lam & 3) * 2;
            size_t base = (((size_t)b * Lr + lt + row0) * Gc + g) * OPG + col;
            *(float2*)(out + base) = make_float2(facc[mi][nj][0], facc[mi][nj][1]);
            *(float2*)(out + base + (size_t)8 * Gc * OPG) =
                make_float2(facc[mi][nj][2], facc[mi][nj][3]);
        }
    }
}

extern "C" void kernel_launch(void* const* d_in, const int* in_sizes, int n_in,
                              void* d_out, int out_size) {
    const float* inp = (const float*)d_in[0];   // (4, 4096, 1024) f32
    const int*   pos = (const int*)d_in[1];     // (4, 4096) i32
    const float* w   = (const float*)d_in[2];   // (16, 64, 64, 5) f32
    float* out = (float*)d_out;                 // (4, 4096, 16, 64) f32

    build_wfrag_kernel<<<Gc * 4, 256>>>(w);     // 64 blocks, coalesced staged pack

    cudaFuncSetAttribute(conv_hmma_kernel,
                         cudaFuncAttributeMaxDynamicSharedMemorySize, SM_TOTAL);
    dim3 grid(Lr / TILE_M, Gc, Br);   // (16, 16, 4)
    conv_hmma_kernel<<<grid, NTHR, SM_TOTAL>>>(inp, pos, out);
}